// round 16
// baseline (speedup 1.0000x reference)
#include <cuda_runtime.h>
#include <math.h>
#include <stdint.h>

// Problem constants
#define BT   61      // 1 + P(10) + N(50) sequences
#define LL   10      // sequence length
#define EE   128     // embedding dim
#define HH   128     // hidden dim
#define GG   384     // 3*H gates
#define NTHR 384
#define QPR  32      // float4 quads per weight row (128 floats)
#define CQ   8       // quads per pipeline chunk
#define RPITCH 9     // float4 pitch per row inside a chunk slot
#define SLOT_F4 (GG * RPITCH)   // 3456 float4 per slot
#define NSLOT 3

// Cross-CTA state (no allocs allowed). g_sync reset by the last CTA each run.
__device__ float g_enc[BT * HH];
__device__ unsigned int g_sync = 0;

// packed fp32x2 FMA: d = a*b + c elementwise on two fp32 lanes (sm_100+)
#define FMA2(d, a, b, c) \
    asm("fma.rn.f32x2 %0, %1, %2, %3;" : "=l"(d) : "l"(a), "l"(b), "l"(c))

#define BAR_SYNC(id, n)   asm volatile("bar.sync %0, %1;"   :: "n"(id), "n"(n) : "memory")
#define BAR_ARRIVE(id, n) asm volatile("bar.arrive %0, %1;" :: "n"(id), "n"(n) : "memory")

__device__ __forceinline__ float2 unpack2(unsigned long long v) {
    float2 r;
    asm("mov.b64 {%0, %1}, %2;" : "=f"(r.x), "=f"(r.y) : "l"(v));
    return r;
}
__device__ __forceinline__ float tanh_apx(float x) {
    float y;
    asm("tanh.approx.f32 %0, %1;" : "=f"(y) : "f"(x));
    return y;
}
__device__ __forceinline__ float sig_apx(float x) {
    return 0.5f * tanh_apx(0.5f * x) + 0.5f;
}
__device__ __forceinline__ void cp16(uint32_t saddr, const void* gaddr) {
    asm volatile("cp.async.ca.shared.global [%0], [%1], 16;" :: "r"(saddr), "l"(gaddr));
}
__device__ __forceinline__ void cp_commit() {
    asm volatile("cp.async.commit_group;");
}
template <int N>
__device__ __forceinline__ void cp_wait() {
    asm volatile("cp.async.wait_group %0;" :: "n"(N));
}

// Dynamic SMEM layout (floats):
//   ws   : 3 * SLOT_F4 * 4 = 41472   (3-slot chunk ring for streamed weights)
//   x_s  : LL*EE  = 1280
//   gi_s : LL*GG  = 3840
//   gh_s : GG     = 384   (also reduction scratch)
//   h_s  : HH     = 128
#define SMEM_FLOATS (NSLOT*SLOT_F4*4 + LL*EE + LL*GG + GG + HH)
#define SMEM_BYTES  (SMEM_FLOATS * 4)

__global__ __launch_bounds__(NTHR, 1)
void gru_fused_kernel(const int* __restrict__ phr,
                      const int* __restrict__ pos,
                      const int* __restrict__ neg,
                      const float* __restrict__ u_emb,
                      const float* __restrict__ v_emb,
                      const float* __restrict__ w_ih,
                      const float* __restrict__ w_hh,
                      const float* __restrict__ b_ih,
                      const float* __restrict__ b_hh,
                      const float* __restrict__ h0,
                      float* __restrict__ out)
{
    extern __shared__ float dsm[];
    float* ws_f  = dsm;                          // chunk ring (3 slots)
    float* x_s   = ws_f + NSLOT * SLOT_F4 * 4;
    float* gi_s  = x_s  + LL * EE;
    float* gh_s  = gi_s + LL * GG;
    float* h_s   = gh_s + GG;

    __shared__ int s_last;
    __shared__ float red_p[12], red_n[12];

    const int t = threadIdx.x;   // gate id 0..383
    const int b = blockIdx.x;    // sequence id 0..60

    const uint32_t sb = (uint32_t)__cvta_generic_to_shared(ws_f);

    // Per-thread prefetch of one chunk: 8 float4s, coalesced (8 quads/row).
    // chunk < 4 -> w_ih quads [8c, 8c+8); chunk >= 4 -> w_hh quads [8(c-4), ...).
    auto prefetch = [&](int chunk) {
        const float4* src = (chunk < 4) ? (const float4*)w_ih : (const float4*)w_hh;
        const int qbase = (chunk & 3) * CQ;
        const int slot  = chunk % NSLOT;
        #pragma unroll
        for (int j = 0; j < 8; ++j) {
            int i   = t + j * NTHR;
            int row = i >> 3, q = i & 7;
            uint32_t saddr = sb + (uint32_t)((slot * SLOT_F4 + row * RPITCH + q) * 16);
            cp16(saddr, src + (size_t)row * QPR + qbase + q);
        }
        cp_commit();
    };

    // ---- gather x (latency-critical; redundant idx loads broadcast via L1) ----
    {
        const float* table = (b == 0) ? u_emb : v_emb;
        const int* ip = (b == 0) ? phr : (b <= 10 ? pos + (b - 1) * LL
                                                  : neg + (b - 11) * LL);
        #pragma unroll
        for (int i = t; i < LL * EE; i += NTHR) {
            int l = i >> 7, c = i & 127;
            int idx = __ldg(ip + l);
            x_s[i] = table[(long long)idx * EE + c];
        }
    }

    // ---- launch first two chunk prefetches ----
    prefetch(0);
    prefetch(1);

    if (t < HH) h_s[t] = h0[t];
    const float bi = b_ih[t];
    const float bh = b_hh[t];

    // ---- streamed pipeline: chunks 0-3 feed gi partial sums, 4-7 fill wr regs ----
    unsigned long long acc[LL];
    #pragma unroll
    for (int l = 0; l < LL; ++l) acc[l] = 0ull;
    ulonglong2 wr[QPR];          // w_hh row of this gate (128 floats)

    #pragma unroll
    for (int c = 0; c < 8; ++c) {
        cp_wait<1>();            // my copies for chunk c done (c+1 may fly)
        __syncthreads();         // everyone's chunk-c copies visible (+x_s on c=0)
        if (c + 2 < 8) prefetch(c + 2);   // slot (c+2)%3: last read iter c-1, safe

        const float* slotp = ws_f + (size_t)(c % NSLOT) * SLOT_F4 * 4;
        const ulonglong2* wrow = (const ulonglong2*)slotp + t * RPITCH;

        if (c < 4) {
            #pragma unroll
            for (int q = 0; q < CQ; ++q) {
                ulonglong2 w = wrow[q];                 // LDS.128
                const int k = c * CQ + q;               // global quad index
                #pragma unroll
                for (int l = 0; l < LL; ++l) {
                    ulonglong2 xv = *(const ulonglong2*)&x_s[l * EE + k * 4]; // bcast
                    FMA2(acc[l], w.x, xv.x, acc[l]);
                    FMA2(acc[l], w.y, xv.y, acc[l]);
                }
            }
            if (c == 3) {
                #pragma unroll
                for (int l = 0; l < LL; ++l) {
                    float2 f = unpack2(acc[l]);
                    gi_s[l * GG + t] = f.x + f.y + bi;
                }
            }
        } else {
            #pragma unroll
            for (int q = 0; q < CQ; ++q)
                wr[(c - 4) * CQ + q] = wrow[q];   // acc[] is dead here -> no spill
        }
    }
    __syncthreads();             // gi_s / wr complete before scan

    // ---- GRU scan: split-barrier producer/consumer, 2 barriers per step ----
    // consumers (t<128) own hidden unit t; producers (t>=128) supply hz/hn.
    // bar1: producers arrive (gh ready, done reading h); consumers sync.
    // bar2: full sync — all h writes visible to everyone before next dot.
    float hreg = (t < HH) ? h_s[t] : 0.f;
    const bool cons = (t < HH);

    for (int l = 0; l < LL; ++l) {
        unsigned long long dA = 0ull, dB = 0ull;
        #pragma unroll
        for (int k = 0; k < 32; k += 2) {
            ulonglong2 h0v = *(const ulonglong2*)&h_s[k * 4];        // bcast
            ulonglong2 h1v = *(const ulonglong2*)&h_s[(k + 1) * 4];  // bcast
            FMA2(dA, wr[k].x,     h0v.x, dA);
            FMA2(dA, wr[k].y,     h0v.y, dA);
            FMA2(dB, wr[k + 1].x, h1v.x, dB);
            FMA2(dB, wr[k + 1].y, h1v.y, dB);
        }
        float2 fa = unpack2(dA), fb = unpack2(dB);
        float ghv = ((fa.x + fa.y) + (fb.x + fb.y)) + bh;

        if (cons) {
            float irv = gi_s[l * GG + t];
            float izv = gi_s[l * GG + t + 128];
            float inv = gi_s[l * GG + t + 256];
            float r = sig_apx(irv + ghv);      // hr_ is our own dot; off critical path
            BAR_SYNC(1, NTHR);                 // producers arrived: gh ready, h free
            float hz = gh_s[t + 128];
            float hn = gh_s[t + 256];
            float z = sig_apx(izv + hz);
            float n = tanh_apx(fmaf(r, hn, inv));
            hreg = fmaf(z, hreg - n, n);       // (1-z)n + z h
            h_s[t] = hreg;
        } else {
            gh_s[t] = ghv;
            BAR_ARRIVE(1, NTHR);               // gh ready -> consumers
        }
        BAR_SYNC(2, NTHR);                     // all h writes visible to all
    }

    // ---- publish final hidden state (single cross-CTA rendezvous) ----
    if (cons) g_enc[b * HH + t] = hreg;
    __syncthreads();                           // ALL g_enc stores precede release

    if (t == 0) {
        __threadfence();                       // release g_enc writes
        unsigned int v = atomicAdd(&g_sync, 1u);
        s_last = (v == BT - 1) ? 1 : 0;
    }
    __syncthreads();

    // ---- last CTA computes ALL dots + loss (no flag spin, one L2 round-trip) ----
    if (s_last) {
        __threadfence();                       // acquire other CTAs' g_enc
        const int w = t >> 5, lane = t & 31;   // 12 warps, 5 sequences each

        // node vector (CTA 0's h), L2-fresh
        float n0 = __ldcg(&g_enc[lane]);
        float n1 = __ldcg(&g_enc[lane + 32]);
        float n2 = __ldcg(&g_enc[lane + 64]);
        float n3 = __ldcg(&g_enc[lane + 96]);

        float P = 0.f, N = 0.f;
        #pragma unroll
        for (int j = 0; j < 5; ++j) {
            int r = 1 + w + 12 * j;            // covers 1..60 exactly
            const float* e = g_enc + r * HH;
            float s = n0 * __ldcg(e + lane) + n1 * __ldcg(e + lane + 32)
                    + n2 * __ldcg(e + lane + 64) + n3 * __ldcg(e + lane + 96);
            #pragma unroll
            for (int o = 16; o; o >>= 1) s += __shfl_xor_sync(0xffffffffu, s, o);
            s *= (1.0f / 128.0f);
            if (r <= 10)      P += s;
            else if (s > 0.f) N += __expf(s);
        }
        if (lane == 0) { red_p[w] = P; red_n[w] = N; }
        __syncthreads();

        if (t == 0) {
            float Ps = 0.f, Ns = 0.f;
            #pragma unroll
            for (int i = 0; i < 12; ++i) { Ps += red_p[i]; Ns += red_n[i]; }
            out[0] = logf(1.f + Ns) - Ps;
            g_sync = 0;                        // reset for next graph replay
        }
    }
}

extern "C" void kernel_launch(void* const* d_in, const int* in_sizes, int n_in,
                              void* d_out, int out_size)
{
    const int*   phr   = (const int*)  d_in[0];
    const int*   pos   = (const int*)  d_in[1];
    const int*   neg   = (const int*)  d_in[2];
    const float* u_emb = (const float*)d_in[3];
    const float* v_emb = (const float*)d_in[4];
    const float* w_ih  = (const float*)d_in[5];
    const float* w_hh  = (const float*)d_in[6];
    const float* b_ih  = (const float*)d_in[7];
    const float* b_hh  = (const float*)d_in[8];
    const float* h0    = (const float*)d_in[9];
    float* out = (float*)d_out;

    cudaFuncSetAttribute(gru_fused_kernel,
                         cudaFuncAttributeMaxDynamicSharedMemorySize, SMEM_BYTES);

    gru_fused_kernel<<<BT, NTHR, SMEM_BYTES>>>(phr, pos, neg, u_emb, v_emb,
                                               w_ih, w_hh, b_ih, b_hh, h0, out);
}

// round 17
// speedup vs baseline: 1.0507x; 1.0507x over previous
#include <cuda_runtime.h>
#include <math.h>
#include <stdint.h>

// Problem constants
#define BT   61      // 1 + P(10) + N(50) sequences
#define LL   10      // sequence length
#define EE   128     // embedding dim
#define HH   128     // hidden dim
#define GG   384     // 3*H gates
#define NTHR 384
#define QPR  32      // float4 quads per weight row (128 floats)
#define CQ   8       // quads per pipeline chunk
#define RPITCH 9     // float4 pitch per row inside a chunk slot
#define SLOT_F4 (GG * RPITCH)   // 3456 float4 per slot
#define NSLOT 3

// Cross-CTA state (no allocs allowed). g_sync reset by the last CTA each run.
__device__ float g_enc[BT * HH];
__device__ unsigned int g_sync = 0;

// packed fp32x2 FMA: d = a*b + c elementwise on two fp32 lanes (sm_100+)
#define FMA2(d, a, b, c) \
    asm("fma.rn.f32x2 %0, %1, %2, %3;" : "=l"(d) : "l"(a), "l"(b), "l"(c))

#define BAR_SYNC(id, n)   asm volatile("bar.sync %0, %1;"   :: "n"(id), "n"(n) : "memory")
#define BAR_ARRIVE(id, n) asm volatile("bar.arrive %0, %1;" :: "n"(id), "n"(n) : "memory")

__device__ __forceinline__ float2 unpack2(unsigned long long v) {
    float2 r;
    asm("mov.b64 {%0, %1}, %2;" : "=f"(r.x), "=f"(r.y) : "l"(v));
    return r;
}
__device__ __forceinline__ float tanh_apx(float x) {
    float y;
    asm("tanh.approx.f32 %0, %1;" : "=f"(y) : "f"(x));
    return y;
}
__device__ __forceinline__ float sig_apx(float x) {
    return 0.5f * tanh_apx(0.5f * x) + 0.5f;
}
__device__ __forceinline__ void cp16(uint32_t saddr, const void* gaddr) {
    asm volatile("cp.async.ca.shared.global [%0], [%1], 16;" :: "r"(saddr), "l"(gaddr));
}
__device__ __forceinline__ void cp_commit() {
    asm volatile("cp.async.commit_group;");
}
template <int N>
__device__ __forceinline__ void cp_wait() {
    asm volatile("cp.async.wait_group %0;" :: "n"(N));
}

// Dynamic SMEM layout (floats):
//   ws   : 3 * SLOT_F4 * 4 = 41472   (3-slot chunk ring for streamed weights)
//   x_s  : LL*EE  = 1280
//   gi_s : LL*GG  = 3840
//   gh_s : GG     = 384   (also reduction scratch)
//   h_s  : HH     = 128
#define SMEM_FLOATS (NSLOT*SLOT_F4*4 + LL*EE + LL*GG + GG + HH)
#define SMEM_BYTES  (SMEM_FLOATS * 4)

__global__ __launch_bounds__(NTHR, 1)
void gru_fused_kernel(const int* __restrict__ phr,
                      const int* __restrict__ pos,
                      const int* __restrict__ neg,
                      const float* __restrict__ u_emb,
                      const float* __restrict__ v_emb,
                      const float* __restrict__ w_ih,
                      const float* __restrict__ w_hh,
                      const float* __restrict__ b_ih,
                      const float* __restrict__ b_hh,
                      const float* __restrict__ h0,
                      float* __restrict__ out)
{
    extern __shared__ float dsm[];
    float* ws_f  = dsm;                          // chunk ring (3 slots)
    float* x_s   = ws_f + NSLOT * SLOT_F4 * 4;
    float* gi_s  = x_s  + LL * EE;
    float* gh_s  = gi_s + LL * GG;
    float* h_s   = gh_s + GG;

    __shared__ int s_last;
    __shared__ float red_p[12], red_n[12];

    const int t = threadIdx.x;   // gate id 0..383
    const int b = blockIdx.x;    // sequence id 0..60

    const uint32_t sb = (uint32_t)__cvta_generic_to_shared(ws_f);

    // Per-thread prefetch of one chunk: 8 float4s, coalesced (8 quads/row).
    // chunk < 4 -> w_ih quads [8c, 8c+8); chunk >= 4 -> w_hh quads [8(c-4), ...).
    auto prefetch = [&](int chunk) {
        const float4* src = (chunk < 4) ? (const float4*)w_ih : (const float4*)w_hh;
        const int qbase = (chunk & 3) * CQ;
        const int slot  = chunk % NSLOT;
        #pragma unroll
        for (int j = 0; j < 8; ++j) {
            int i   = t + j * NTHR;
            int row = i >> 3, q = i & 7;
            uint32_t saddr = sb + (uint32_t)((slot * SLOT_F4 + row * RPITCH + q) * 16);
            cp16(saddr, src + (size_t)row * QPR + qbase + q);
        }
        cp_commit();
    };

    // ---- launch first two chunk prefetches FIRST (cp.async is asm volatile:
    //      if issued after the gather's STS loop it cannot start until the
    //      gather's dependent DRAM chain resolves — ~1K cycles of pipeline
    //      serialization). Issued here, weights stream while we gather x. ----
    prefetch(0);
    prefetch(1);

    // ---- gather x (overlaps with chunk 0/1 flight; STS drained by c=0 BAR) ----
    {
        const float* table = (b == 0) ? u_emb : v_emb;
        const int* ip = (b == 0) ? phr : (b <= 10 ? pos + (b - 1) * LL
                                                  : neg + (b - 11) * LL);
        #pragma unroll
        for (int i = t; i < LL * EE; i += NTHR) {
            int l = i >> 7, c = i & 127;
            int idx = __ldg(ip + l);
            x_s[i] = table[(long long)idx * EE + c];
        }
    }

    if (t < HH) h_s[t] = h0[t];
    const float bi = b_ih[t];
    const float bh = b_hh[t];

    // ---- streamed pipeline: chunks 0-3 feed gi partial sums, 4-7 fill wr regs ----
    unsigned long long acc[LL];
    #pragma unroll
    for (int l = 0; l < LL; ++l) acc[l] = 0ull;
    ulonglong2 wr[QPR];          // w_hh row of this gate (128 floats)

    #pragma unroll
    for (int c = 0; c < 8; ++c) {
        cp_wait<1>();            // my copies for chunk c done (c+1 may fly)
        __syncthreads();         // everyone's chunk-c copies visible (+x_s on c=0)
        if (c + 2 < 8) prefetch(c + 2);   // slot (c+2)%3: last read iter c-1, safe

        const float* slotp = ws_f + (size_t)(c % NSLOT) * SLOT_F4 * 4;
        const ulonglong2* wrow = (const ulonglong2*)slotp + t * RPITCH;

        if (c < 4) {
            #pragma unroll
            for (int q = 0; q < CQ; ++q) {
                ulonglong2 w = wrow[q];                 // LDS.128
                const int k = c * CQ + q;               // global quad index
                #pragma unroll
                for (int l = 0; l < LL; ++l) {
                    ulonglong2 xv = *(const ulonglong2*)&x_s[l * EE + k * 4]; // bcast
                    FMA2(acc[l], w.x, xv.x, acc[l]);
                    FMA2(acc[l], w.y, xv.y, acc[l]);
                }
            }
            if (c == 3) {
                #pragma unroll
                for (int l = 0; l < LL; ++l) {
                    float2 f = unpack2(acc[l]);
                    gi_s[l * GG + t] = f.x + f.y + bi;
                }
            }
        } else {
            #pragma unroll
            for (int q = 0; q < CQ; ++q)
                wr[(c - 4) * CQ + q] = wrow[q];   // acc[] is dead here -> no spill
        }
    }
    __syncthreads();             // gi_s / wr complete before scan

    // ---- GRU scan: split-barrier producer/consumer, 2 barriers per step ----
    // consumers (t<128) own hidden unit t; producers (t>=128) supply hz/hn.
    // bar1: producers arrive (gh ready, done reading h); consumers sync.
    // bar2: full sync — all h writes visible to everyone before next dot.
    float hreg = (t < HH) ? h_s[t] : 0.f;
    const bool cons = (t < HH);

    for (int l = 0; l < LL; ++l) {
        unsigned long long dA = 0ull, dB = 0ull;
        #pragma unroll
        for (int k = 0; k < 32; k += 2) {
            ulonglong2 h0v = *(const ulonglong2*)&h_s[k * 4];        // bcast
            ulonglong2 h1v = *(const ulonglong2*)&h_s[(k + 1) * 4];  // bcast
            FMA2(dA, wr[k].x,     h0v.x, dA);
            FMA2(dA, wr[k].y,     h0v.y, dA);
            FMA2(dB, wr[k + 1].x, h1v.x, dB);
            FMA2(dB, wr[k + 1].y, h1v.y, dB);
        }
        float2 fa = unpack2(dA), fb = unpack2(dB);
        float ghv = ((fa.x + fa.y) + (fb.x + fb.y)) + bh;

        if (cons) {
            float irv = gi_s[l * GG + t];
            float izv = gi_s[l * GG + t + 128];
            float inv = gi_s[l * GG + t + 256];
            float r = sig_apx(irv + ghv);      // hr_ is our own dot; off critical path
            BAR_SYNC(1, NTHR);                 // producers arrived: gh ready, h free
            float hz = gh_s[t + 128];
            float hn = gh_s[t + 256];
            float z = sig_apx(izv + hz);
            float n = tanh_apx(fmaf(r, hn, inv));
            hreg = fmaf(z, hreg - n, n);       // (1-z)n + z h
            h_s[t] = hreg;
        } else {
            gh_s[t] = ghv;
            BAR_ARRIVE(1, NTHR);               // gh ready -> consumers
        }
        BAR_SYNC(2, NTHR);                     // all h writes visible to all
    }

    // ---- publish final hidden state (single cross-CTA rendezvous) ----
    if (cons) g_enc[b * HH + t] = hreg;
    __syncthreads();                           // ALL g_enc stores precede release

    if (t == 0) {
        __threadfence();                       // release g_enc writes
        unsigned int v = atomicAdd(&g_sync, 1u);
        s_last = (v == BT - 1) ? 1 : 0;
    }
    __syncthreads();

    // ---- last CTA computes ALL dots + loss (no flag spin, one L2 round-trip) ----
    if (s_last) {
        __threadfence();                       // acquire other CTAs' g_enc
        const int w = t >> 5, lane = t & 31;   // 12 warps, 5 sequences each

        // node vector (CTA 0's h), L2-fresh
        float n0 = __ldcg(&g_enc[lane]);
        float n1 = __ldcg(&g_enc[lane + 32]);
        float n2 = __ldcg(&g_enc[lane + 64]);
        float n3 = __ldcg(&g_enc[lane + 96]);

        float P = 0.f, N = 0.f;
        #pragma unroll
        for (int j = 0; j < 5; ++j) {
            int r = 1 + w + 12 * j;            // covers 1..60 exactly
            const float* e = g_enc + r * HH;
            float s = n0 * __ldcg(e + lane) + n1 * __ldcg(e + lane + 32)
                    + n2 * __ldcg(e + lane + 64) + n3 * __ldcg(e + lane + 96);
            #pragma unroll
            for (int o = 16; o; o >>= 1) s += __shfl_xor_sync(0xffffffffu, s, o);
            s *= (1.0f / 128.0f);
            if (r <= 10)      P += s;
            else if (s > 0.f) N += __expf(s);
        }
        if (lane == 0) { red_p[w] = P; red_n[w] = N; }
        __syncthreads();

        if (t == 0) {
            float Ps = 0.f, Ns = 0.f;
            #pragma unroll
            for (int i = 0; i < 12; ++i) { Ps += red_p[i]; Ns += red_n[i]; }
            out[0] = logf(1.f + Ns) - Ps;
            g_sync = 0;                        // reset for next graph replay
        }
    }
}

extern "C" void kernel_launch(void* const* d_in, const int* in_sizes, int n_in,
                              void* d_out, int out_size)
{
    const int*   phr   = (const int*)  d_in[0];
    const int*   pos   = (const int*)  d_in[1];
    const int*   neg   = (const int*)  d_in[2];
    const float* u_emb = (const float*)d_in[3];
    const float* v_emb = (const float*)d_in[4];
    const float* w_ih  = (const float*)d_in[5];
    const float* w_hh  = (const float*)d_in[6];
    const float* b_ih  = (const float*)d_in[7];
    const float* b_hh  = (const float*)d_in[8];
    const float* h0    = (const float*)d_in[9];
    float* out = (float*)d_out;

    cudaFuncSetAttribute(gru_fused_kernel,
                         cudaFuncAttributeMaxDynamicSharedMemorySize, SMEM_BYTES);

    gru_fused_kernel<<<BT, NTHR, SMEM_BYTES>>>(phr, pos, neg, u_emb, v_emb,
                                               w_ih, w_hh, b_ih, b_hh, h0, out);
}